// round 1
// baseline (speedup 1.0000x reference)
#include <cuda_runtime.h>

#define NN   4096
#define FEAT 1024
#define GC   10
#define HD   5

// Scratch (no allocations allowed)
__device__ float g_s[NN];          // D^{-1/2} diagonal
__device__ float g_M[NN * GC];     // projected features (input to Ahat@)
__device__ float g_H[NN * GC];     // selu(Ahat@M) output

__device__ __forceinline__ float sigf(float v) {
    return 1.0f / (1.0f + __expf(-v));
}
__device__ __forceinline__ float mytanh(float v) {
    // 2*sigmoid(2v)-1 : safe at +-inf, accurate near 0
    return 2.0f / (1.0f + __expf(-2.0f * v)) - 1.0f;
}
__device__ __forceinline__ float seluf(float v) {
    // scale = 1.0507009873554805, scale*alpha = 1.7580993408473766
    return v > 0.0f ? 1.0507009873554805f * v
                    : 1.7580993408473766f * (__expf(v) - 1.0f);
}

// ---------------------------------------------------------------------------
// K1: row sums of A -> s_i = deg>0 ? rsqrt(deg) : 0
// ---------------------------------------------------------------------------
__global__ void k_rowsum(const float* __restrict__ A) {
    int row = blockIdx.x;
    const float4* a4 = (const float4*)(A + (size_t)row * NN);
    float s = 0.0f;
    for (int i = threadIdx.x; i < NN / 4; i += blockDim.x) {
        float4 v = a4[i];
        s += (v.x + v.y) + (v.z + v.w);
    }
    __shared__ float red[8];
    #pragma unroll
    for (int o = 16; o; o >>= 1) s += __shfl_xor_sync(0xffffffffu, s, o);
    if ((threadIdx.x & 31) == 0) red[threadIdx.x >> 5] = s;
    __syncthreads();
    if (threadIdx.x < 32) {
        float v = (threadIdx.x < (blockDim.x >> 5)) ? red[threadIdx.x] : 0.0f;
        #pragma unroll
        for (int o = 4; o; o >>= 1) v += __shfl_xor_sync(0xffffffffu, v, o);
        if (threadIdx.x == 0) g_s[row] = v > 0.0f ? rsqrtf(v) : 0.0f;
    }
}

// ---------------------------------------------------------------------------
// K2: g_M = X @ W0^T   (4096x1024 @ 1024x10). One warp per row.
// ---------------------------------------------------------------------------
__global__ void k_xw(const float* __restrict__ X, const float* __restrict__ W0) {
    int row  = blockIdx.x * blockDim.y + threadIdx.y;
    int lane = threadIdx.x;
    const float* xr = X + (size_t)row * FEAT;
    float acc[GC];
    #pragma unroll
    for (int k = 0; k < GC; k++) acc[k] = 0.0f;
    for (int m = 0; m < FEAT / 32; m++) {
        int j = m * 32 + lane;
        float xv = xr[j];
        #pragma unroll
        for (int k = 0; k < GC; k++) acc[k] += xv * W0[k * FEAT + j];
    }
    #pragma unroll
    for (int k = 0; k < GC; k++) {
        #pragma unroll
        for (int o = 16; o; o >>= 1)
            acc[k] += __shfl_xor_sync(0xffffffffu, acc[k], o);
    }
    if (lane == 0) {
        #pragma unroll
        for (int k = 0; k < GC; k++) g_M[row * GC + k] = acc[k];
    }
}

// ---------------------------------------------------------------------------
// K3: g_H = selu( Ahat @ g_M )  without materializing Ahat.
// Block: 256 threads, 16 rows per block, 16 threads per row.
// Z (= s_j * M_j) staged in smem, padded to 12 floats/row for float4 loads.
// ---------------------------------------------------------------------------
#define RPB 16
#define JC  1024
__global__ void k_spmm(const float* __restrict__ A) {
    __shared__ __align__(16) float Zs[JC * 12];
    int rowbase = blockIdx.x * RPB;
    int sub = threadIdx.x & 15;
    int r   = threadIdx.x >> 4;
    int row = rowbase + r;
    float acc[GC];
    #pragma unroll
    for (int k = 0; k < GC; k++) acc[k] = 0.0f;

    for (int jb = 0; jb < NN; jb += JC) {
        __syncthreads();
        for (int t = threadIdx.x; t < JC; t += blockDim.x) {
            int j = jb + t;
            float sj = g_s[j];
            #pragma unroll
            for (int k = 0; k < GC; k++) Zs[t * 12 + k] = sj * g_M[j * GC + k];
        }
        __syncthreads();
        const float* ar = A + (size_t)row * NN + jb;
        for (int m = 0; m < JC / 16; m++) {
            int jj = sub + m * 16;
            float a = ar[jj];
            float4 z0 = *(const float4*)&Zs[jj * 12];
            float4 z1 = *(const float4*)&Zs[jj * 12 + 4];
            float2 z2 = *(const float2*)&Zs[jj * 12 + 8];
            acc[0] += a * z0.x; acc[1] += a * z0.y;
            acc[2] += a * z0.z; acc[3] += a * z0.w;
            acc[4] += a * z1.x; acc[5] += a * z1.y;
            acc[6] += a * z1.z; acc[7] += a * z1.w;
            acc[8] += a * z2.x; acc[9] += a * z2.y;
        }
    }
    #pragma unroll
    for (int k = 0; k < GC; k++) {
        #pragma unroll
        for (int o = 8; o; o >>= 1)
            acc[k] += __shfl_xor_sync(0xffffffffu, acc[k], o);
    }
    if (sub == 0) {
        float si = g_s[row];
        #pragma unroll
        for (int k = 0; k < GC; k++) {
            float v = si * acc[k] + si * si * g_M[row * GC + k];
            g_H[row * GC + k] = seluf(v);
        }
    }
}

// ---------------------------------------------------------------------------
// K4: g_M = g_H @ W^T   (10x10 per row)
// ---------------------------------------------------------------------------
__global__ void k_hw(const float* __restrict__ W) {
    int i = blockIdx.x * blockDim.x + threadIdx.x;
    if (i >= NN) return;
    float h[GC];
    #pragma unroll
    for (int k = 0; k < GC; k++) h[k] = g_H[i * GC + k];
    #pragma unroll
    for (int ko = 0; ko < GC; ko++) {
        float s = 0.0f;
        #pragma unroll
        for (int k = 0; k < GC; k++) s += h[k] * W[ko * GC + k];
        g_M[i * GC + ko] = s;
    }
}

// ---------------------------------------------------------------------------
// K5: full encode+decode LSTM in a single warp (latency-bound serial chain).
// Lane layout per layer:
//   gate lanes 0..19: gate g = lane for dir0 (regs A) and dir1 (regs B)
//   combine lanes 0..9: lane = d*5 + j  holds (h,c) state for cell (layer,d,j)
// All cross-lane traffic via shuffles; no barriers.
// ---------------------------------------------------------------------------
__global__ void __launch_bounds__(32, 1) k_lstm(
    const float* __restrict__ Wih_g, const float* __restrict__ Whh_g,
    const float* __restrict__ bih_g, const float* __restrict__ bhh_g,
    const float* __restrict__ h0_g,  const float* __restrict__ c0_g,
    const float* __restrict__ tok_g, const float* __restrict__ Wo_g,
    const float* __restrict__ bo_g,  float* __restrict__ out)
{
    const int lane = threadIdx.x;
    const int g = (lane < 20) ? lane : 0;          // clamp for weight loads
    const bool isg = (lane >= 10 && lane < 15);    // tanh gate lanes
    const int cl = (lane < 10) ? lane : 0;         // clamp for state lanes
    const int dsel = cl / 5;                        // direction of combine lane
    const int jj = cl % 5;                          // hidden index of combine lane

    // Per-lane weights: [layer][dir]
    float wih[3][2][GC], whh[3][2][HD], bias[3][2];
    #pragma unroll
    for (int l = 0; l < 3; l++) {
        #pragma unroll
        for (int d = 0; d < 2; d++) {
            int k = 2 * l + d;
            #pragma unroll
            for (int i = 0; i < GC; i++) wih[l][d][i] = Wih_g[(k * 20 + g) * GC + i];
            #pragma unroll
            for (int i = 0; i < HD; i++) whh[l][d][i] = Whh_g[(k * 20 + g) * HD + i];
            bias[l][d] = bih_g[k * 20 + g] + bhh_g[k * 20 + g];
        }
    }
    // States (meaningful only on lanes 0..9)
    float hst[3], cst[3];
    #pragma unroll
    for (int l = 0; l < 3; l++) {
        int k = 2 * l + dsel;
        hst[l] = h0_g[k * HD + jj];
        cst[l] = c0_g[k * HD + jj];
    }
    // Output head weights (all lanes load, lane0 uses)
    float wov[GC];
    #pragma unroll
    for (int i = 0; i < GC; i++) wov[i] = Wo_g[i];
    const float bo0 = bo_g[0];

    float x[GC], xn[GC];

#define LSTM_STEP()                                                             \
    do {                                                                        \
        _Pragma("unroll")                                                       \
        for (int l = 0; l < 3; l++) {                                           \
            float hA[HD], hB[HD];                                               \
            _Pragma("unroll")                                                   \
            for (int j2 = 0; j2 < HD; j2++) {                                   \
                hA[j2] = __shfl_sync(0xffffffffu, hst[l], j2);                  \
                hB[j2] = __shfl_sync(0xffffffffu, hst[l], HD + j2);             \
            }                                                                   \
            float a0 = bias[l][0], a1 = 0.0f, a2 = 0.0f;                        \
            float b0 = bias[l][1], b1 = 0.0f, b2 = 0.0f;                        \
            _Pragma("unroll")                                                   \
            for (int i = 0; i < 5; i++) {                                       \
                a0 += wih[l][0][i] * x[i]; b0 += wih[l][1][i] * x[i];           \
            }                                                                   \
            _Pragma("unroll")                                                   \
            for (int i = 5; i < 10; i++) {                                      \
                a1 += wih[l][0][i] * x[i]; b1 += wih[l][1][i] * x[i];           \
            }                                                                   \
            _Pragma("unroll")                                                   \
            for (int i = 0; i < 5; i++) {                                       \
                a2 += whh[l][0][i] * hA[i]; b2 += whh[l][1][i] * hB[i];         \
            }                                                                   \
            float gA = (a0 + a1) + a2;                                          \
            float gB = (b0 + b1) + b2;                                          \
            float uA = isg ? gA + gA : gA;                                      \
            float sA = sigf(uA);                                                \
            float aA = isg ? 2.0f * sA - 1.0f : sA;                             \
            float uB = isg ? gB + gB : gB;                                      \
            float sB = sigf(uB);                                                \
            float aB = isg ? 2.0f * sB - 1.0f : sB;                             \
            float i0 = __shfl_sync(0xffffffffu, aA, jj);                        \
            float i1 = __shfl_sync(0xffffffffu, aB, jj);                        \
            float f0 = __shfl_sync(0xffffffffu, aA, HD + jj);                   \
            float f1 = __shfl_sync(0xffffffffu, aB, HD + jj);                   \
            float q0 = __shfl_sync(0xffffffffu, aA, 10 + jj);                   \
            float q1 = __shfl_sync(0xffffffffu, aB, 10 + jj);                   \
            float o0 = __shfl_sync(0xffffffffu, aA, 15 + jj);                   \
            float o1 = __shfl_sync(0xffffffffu, aB, 15 + jj);                   \
            float iv = dsel ? i1 : i0;                                          \
            float fv = dsel ? f1 : f0;                                          \
            float qv = dsel ? q1 : q0;                                          \
            float ov = dsel ? o1 : o0;                                          \
            float cn = fv * cst[l] + iv * qv;                                   \
            float hn = ov * mytanh(cn);                                         \
            cst[l] = cn; hst[l] = hn;                                           \
            _Pragma("unroll")                                                   \
            for (int i = 0; i < GC; i++)                                        \
                x[i] = __shfl_sync(0xffffffffu, hn, i);                         \
        }                                                                       \
    } while (0)

    // ---------------- Encoder: feed H3 rows, one per timestep ----------------
    #pragma unroll
    for (int i = 0; i < GC; i++) x[i] = g_H[i];
    for (int t = 0; t < NN; t++) {
        int tp = (t + 1 < NN) ? t + 1 : t;
        #pragma unroll
        for (int i = 0; i < GC; i++) xn[i] = g_H[tp * GC + i];  // prefetch
        LSTM_STEP();
        #pragma unroll
        for (int i = 0; i < GC; i++) x[i] = xn[i];              // discard step out
    }

    // ---------------- Decoder: autoregressive --------------------------------
    #pragma unroll
    for (int i = 0; i < GC; i++) x[i] = tok_g[i];
    for (int t = 0; t < NN; t++) {
        LSTM_STEP();
        if (lane == 0) {
            float z = bo0;
            #pragma unroll
            for (int i = 0; i < GC; i++) z += x[i] * wov[i];
            out[t] = sigf(z);
        }
    }
#undef LSTM_STEP
}

// ---------------------------------------------------------------------------
extern "C" void kernel_launch(void* const* d_in, const int* in_sizes, int n_in,
                              void* d_out, int out_size)
{
    const float* A   = (const float*)d_in[0];
    const float* X   = (const float*)d_in[1];
    const float* W0  = (const float*)d_in[2];
    const float* W1  = (const float*)d_in[3];
    const float* W2  = (const float*)d_in[4];
    const float* Wih = (const float*)d_in[5];
    const float* Whh = (const float*)d_in[6];
    const float* bih = (const float*)d_in[7];
    const float* bhh = (const float*)d_in[8];
    const float* h0  = (const float*)d_in[9];
    const float* c0  = (const float*)d_in[10];
    const float* tok = (const float*)d_in[11];
    const float* Wo  = (const float*)d_in[12];
    const float* bo  = (const float*)d_in[13];
    float* out = (float*)d_out;
    (void)in_sizes; (void)n_in; (void)out_size;

    k_rowsum<<<NN, 256>>>(A);
    k_xw<<<NN / 8, dim3(32, 8)>>>(X, W0);        // g_M = X @ W0^T
    k_spmm<<<NN / RPB, 256>>>(A);                // g_H = selu(Ahat @ g_M)
    k_hw<<<(NN + 255) / 256, 256>>>(W1);         // g_M = g_H @ W1^T
    k_spmm<<<NN / RPB, 256>>>(A);
    k_hw<<<(NN + 255) / 256, 256>>>(W2);         // g_M = g_H @ W2^T
    k_spmm<<<NN / RPB, 256>>>(A);                // g_H = H3 (encoder inputs)
    k_lstm<<<1, 32>>>(Wih, Whh, bih, bhh, h0, c0, tok, Wo, bo, out);
}

// round 2
// speedup vs baseline: 1.4037x; 1.4037x over previous
#include <cuda_runtime.h>

#define NN   4096
#define FEAT 1024
#define GC   10
#define HD   5

// Scratch (no allocations allowed)
__device__ float g_s[NN];          // D^{-1/2} diagonal
__device__ float g_M[NN * GC];     // projected features (input to Ahat@)
__device__ float g_H[NN * GC];     // selu(Ahat@M) output

__device__ __forceinline__ float tanha(float x) {
    float y;
    asm("tanh.approx.f32 %0, %1;" : "=f"(y) : "f"(x));
    return y;
}
__device__ __forceinline__ float siga(float x) {        // sigmoid via MUFU.TANH
    return fmaf(0.5f, tanha(0.5f * x), 0.5f);
}
__device__ __forceinline__ float sig_exact(float v) {   // for output head only
    return 1.0f / (1.0f + __expf(-v));
}
__device__ __forceinline__ float seluf(float v) {
    return v > 0.0f ? 1.0507009873554805f * v
                    : 1.7580993408473766f * (__expf(v) - 1.0f);
}

// ---------------------------------------------------------------------------
// K1: row sums of A -> s_i = deg>0 ? rsqrt(deg) : 0
// ---------------------------------------------------------------------------
__global__ void k_rowsum(const float* __restrict__ A) {
    int row = blockIdx.x;
    const float4* a4 = (const float4*)(A + (size_t)row * NN);
    float s = 0.0f;
    for (int i = threadIdx.x; i < NN / 4; i += blockDim.x) {
        float4 v = a4[i];
        s += (v.x + v.y) + (v.z + v.w);
    }
    __shared__ float red[8];
    #pragma unroll
    for (int o = 16; o; o >>= 1) s += __shfl_xor_sync(0xffffffffu, s, o);
    if ((threadIdx.x & 31) == 0) red[threadIdx.x >> 5] = s;
    __syncthreads();
    if (threadIdx.x < 32) {
        float v = (threadIdx.x < (blockDim.x >> 5)) ? red[threadIdx.x] : 0.0f;
        #pragma unroll
        for (int o = 4; o; o >>= 1) v += __shfl_xor_sync(0xffffffffu, v, o);
        if (threadIdx.x == 0) g_s[row] = v > 0.0f ? rsqrtf(v) : 0.0f;
    }
}

// ---------------------------------------------------------------------------
// K2: g_M = X @ W0^T   (4096x1024 @ 1024x10). One warp per row.
// ---------------------------------------------------------------------------
__global__ void k_xw(const float* __restrict__ X, const float* __restrict__ W0) {
    int row  = blockIdx.x * blockDim.y + threadIdx.y;
    int lane = threadIdx.x;
    const float* xr = X + (size_t)row * FEAT;
    float acc[GC];
    #pragma unroll
    for (int k = 0; k < GC; k++) acc[k] = 0.0f;
    for (int m = 0; m < FEAT / 32; m++) {
        int j = m * 32 + lane;
        float xv = xr[j];
        #pragma unroll
        for (int k = 0; k < GC; k++) acc[k] += xv * W0[k * FEAT + j];
    }
    #pragma unroll
    for (int k = 0; k < GC; k++) {
        #pragma unroll
        for (int o = 16; o; o >>= 1)
            acc[k] += __shfl_xor_sync(0xffffffffu, acc[k], o);
    }
    if (lane == 0) {
        #pragma unroll
        for (int k = 0; k < GC; k++) g_M[row * GC + k] = acc[k];
    }
}

// ---------------------------------------------------------------------------
// K3: g_H = selu( Ahat @ g_M )  without materializing Ahat.
// ---------------------------------------------------------------------------
#define RPB 16
#define JC  1024
__global__ void k_spmm(const float* __restrict__ A) {
    __shared__ __align__(16) float Zs[JC * 12];
    int rowbase = blockIdx.x * RPB;
    int sub = threadIdx.x & 15;
    int r   = threadIdx.x >> 4;
    int row = rowbase + r;
    float acc[GC];
    #pragma unroll
    for (int k = 0; k < GC; k++) acc[k] = 0.0f;

    for (int jb = 0; jb < NN; jb += JC) {
        __syncthreads();
        for (int t = threadIdx.x; t < JC; t += blockDim.x) {
            int j = jb + t;
            float sj = g_s[j];
            #pragma unroll
            for (int k = 0; k < GC; k++) Zs[t * 12 + k] = sj * g_M[j * GC + k];
        }
        __syncthreads();
        const float* ar = A + (size_t)row * NN + jb;
        for (int m = 0; m < JC / 16; m++) {
            int jj = sub + m * 16;
            float a = ar[jj];
            float4 z0 = *(const float4*)&Zs[jj * 12];
            float4 z1 = *(const float4*)&Zs[jj * 12 + 4];
            float2 z2 = *(const float2*)&Zs[jj * 12 + 8];
            acc[0] += a * z0.x; acc[1] += a * z0.y;
            acc[2] += a * z0.z; acc[3] += a * z0.w;
            acc[4] += a * z1.x; acc[5] += a * z1.y;
            acc[6] += a * z1.z; acc[7] += a * z1.w;
            acc[8] += a * z2.x; acc[9] += a * z2.y;
        }
    }
    #pragma unroll
    for (int k = 0; k < GC; k++) {
        #pragma unroll
        for (int o = 8; o; o >>= 1)
            acc[k] += __shfl_xor_sync(0xffffffffu, acc[k], o);
    }
    if (sub == 0) {
        float si = g_s[row];
        #pragma unroll
        for (int k = 0; k < GC; k++) {
            float v = si * acc[k] + si * si * g_M[row * GC + k];
            g_H[row * GC + k] = seluf(v);
        }
    }
}

// ---------------------------------------------------------------------------
// K4: g_M = g_H @ W^T   (10x10 per row)
// ---------------------------------------------------------------------------
__global__ void k_hw(const float* __restrict__ W) {
    int i = blockIdx.x * blockDim.x + threadIdx.x;
    if (i >= NN) return;
    float h[GC];
    #pragma unroll
    for (int k = 0; k < GC; k++) h[k] = g_H[i * GC + k];
    #pragma unroll
    for (int ko = 0; ko < GC; ko++) {
        float s = 0.0f;
        #pragma unroll
        for (int k = 0; k < GC; k++) s += h[k] * W[ko * GC + k];
        g_M[i * GC + ko] = s;
    }
}

// ---------------------------------------------------------------------------
// K5: encode+decode LSTM, single warp, state-owner lane layout.
// lane = l*10 + d*5 + j  (30 active lanes). Each lane owns cell (layer l,
// dir d, hidden j): computes its own 4 gates (15-term dots, ILP across
// gates), updates (h,c). Per layer only ONE shuffle stage (broadcast of the
// 10 layer outputs); the recurrent h_prev is cached from that broadcast.
// Activations via MUFU.TANH (tanh.approx.f32).
// ---------------------------------------------------------------------------
__global__ void __launch_bounds__(32, 1) k_lstm(
    const float* __restrict__ Wih_g, const float* __restrict__ Whh_g,
    const float* __restrict__ bih_g, const float* __restrict__ bhh_g,
    const float* __restrict__ h0_g,  const float* __restrict__ c0_g,
    const float* __restrict__ tok_g, const float* __restrict__ Wo_g,
    const float* __restrict__ bo_g,  float* __restrict__ out)
{
    const int lane = threadIdx.x;
    const int li   = (lane < 30) ? lane : 29;   // clamp idle lanes
    const int myl  = li / 10;                    // my layer
    const int r    = li % 10;
    const int dsel = r / 5;                      // my direction
    const int j    = r % 5;                      // my hidden index
    const int kc   = 2 * myl + dsel;             // cell index

    // Per-lane weights: gate q row = kc*20 + q*5 + j  (PyTorch gate order i,f,g,o)
    float wih[4][GC], whh[4][HD], bias[4];
    #pragma unroll
    for (int q = 0; q < 4; q++) {
        int row = kc * 20 + q * 5 + j;
        #pragma unroll
        for (int i = 0; i < GC; i++) wih[q][i] = Wih_g[row * GC + i];
        #pragma unroll
        for (int i = 0; i < HD; i++) whh[q][i] = Whh_g[row * HD + i];
        bias[q] = bih_g[row] + bhh_g[row];
    }
    float h = h0_g[kc * HD + j];
    float c = c0_g[kc * HD + j];
    float hp[HD];                               // prev-step h of my (layer,dir)
    #pragma unroll
    for (int i = 0; i < HD; i++) hp[i] = h0_g[kc * HD + i];

    float wov[GC];
    #pragma unroll
    for (int i = 0; i < GC; i++) wov[i] = Wo_g[i];
    const float bo0 = bo_g[0];

    float x[GC], xn[GC], nx[GC];

#define STEP()                                                                  \
    do {                                                                        \
        _Pragma("unroll")                                                       \
        for (int l = 0; l < 3; l++) {                                           \
            float a0[4], a1[4], a2[4];                                          \
            _Pragma("unroll")                                                   \
            for (int q = 0; q < 4; q++) { a0[q] = bias[q]; a1[q] = 0.0f; a2[q] = 0.0f; } \
            _Pragma("unroll")                                                   \
            for (int i = 0; i < 5; i++) {                                       \
                _Pragma("unroll")                                               \
                for (int q = 0; q < 4; q++) a0[q] = fmaf(wih[q][i], x[i], a0[q]); \
            }                                                                   \
            _Pragma("unroll")                                                   \
            for (int i = 5; i < 10; i++) {                                      \
                _Pragma("unroll")                                               \
                for (int q = 0; q < 4; q++) a1[q] = fmaf(wih[q][i], x[i], a1[q]); \
            }                                                                   \
            _Pragma("unroll")                                                   \
            for (int i = 0; i < 5; i++) {                                       \
                _Pragma("unroll")                                               \
                for (int q = 0; q < 4; q++) a2[q] = fmaf(whh[q][i], hp[i], a2[q]); \
            }                                                                   \
            float gi = (a0[0] + a1[0]) + a2[0];                                 \
            float gf = (a0[1] + a1[1]) + a2[1];                                 \
            float gg = (a0[2] + a1[2]) + a2[2];                                 \
            float go = (a0[3] + a1[3]) + a2[3];                                 \
            float ai = siga(gi);                                                \
            float af = siga(gf);                                                \
            float ag = tanha(gg);                                               \
            float ao = siga(go);                                                \
            float cn = fmaf(af, c, ai * ag);                                    \
            float hn = ao * tanha(cn);                                          \
            if (myl == l) { c = cn; h = hn; }                                   \
            _Pragma("unroll")                                                   \
            for (int m = 0; m < GC; m++)                                        \
                nx[m] = __shfl_sync(0xffffffffu, h, l * 10 + m);                \
            if (myl == l) {                                                     \
                _Pragma("unroll")                                               \
                for (int i = 0; i < HD; i++) hp[i] = nx[dsel * 5 + i];          \
            }                                                                   \
            if (myl == l + 1) {                                                 \
                _Pragma("unroll")                                               \
                for (int i = 0; i < GC; i++) x[i] = nx[i];                      \
            }                                                                   \
        }                                                                       \
    } while (0)

    // ---------------- Encoder ----------------
    #pragma unroll
    for (int i = 0; i < GC; i++) x[i] = g_H[i];
    for (int t = 0; t < NN; t++) {
        int tp = (t + 1 < NN) ? t + 1 : t;
        #pragma unroll
        for (int i = 0; i < GC; i++) xn[i] = g_H[tp * GC + i];  // prefetch
        STEP();
        #pragma unroll
        for (int i = 0; i < GC; i++) x[i] = xn[i];
    }

    // ---------------- Decoder (autoregressive) ----------------
    #pragma unroll
    for (int i = 0; i < GC; i++) x[i] = tok_g[i];
    for (int t = 0; t < NN; t++) {
        STEP();
        // nx now holds layer-2 output on all lanes: feed back + output head
        float z = bo0;
        #pragma unroll
        for (int i = 0; i < GC; i++) z = fmaf(nx[i], wov[i], z);
        if (lane == 0) out[t] = sig_exact(z);
        #pragma unroll
        for (int i = 0; i < GC; i++) x[i] = nx[i];
    }
#undef STEP
}

// ---------------------------------------------------------------------------
extern "C" void kernel_launch(void* const* d_in, const int* in_sizes, int n_in,
                              void* d_out, int out_size)
{
    const float* A   = (const float*)d_in[0];
    const float* X   = (const float*)d_in[1];
    const float* W0  = (const float*)d_in[2];
    const float* W1  = (const float*)d_in[3];
    const float* W2  = (const float*)d_in[4];
    const float* Wih = (const float*)d_in[5];
    const float* Whh = (const float*)d_in[6];
    const float* bih = (const float*)d_in[7];
    const float* bhh = (const float*)d_in[8];
    const float* h0  = (const float*)d_in[9];
    const float* c0  = (const float*)d_in[10];
    const float* tok = (const float*)d_in[11];
    const float* Wo  = (const float*)d_in[12];
    const float* bo  = (const float*)d_in[13];
    float* out = (float*)d_out;
    (void)in_sizes; (void)n_in; (void)out_size;

    k_rowsum<<<NN, 256>>>(A);
    k_xw<<<NN / 8, dim3(32, 8)>>>(X, W0);        // g_M = X @ W0^T
    k_spmm<<<NN / RPB, 256>>>(A);                // g_H = selu(Ahat @ g_M)
    k_hw<<<(NN + 255) / 256, 256>>>(W1);         // g_M = g_H @ W1^T
    k_spmm<<<NN / RPB, 256>>>(A);
    k_hw<<<(NN + 255) / 256, 256>>>(W2);         // g_M = g_H @ W2^T
    k_spmm<<<NN / RPB, 256>>>(A);                // g_H = H3 (encoder inputs)
    k_lstm<<<1, 32>>>(Wih, Whh, bih, bhh, h0, c0, tok, Wo, bo, out);
}

// round 4
// speedup vs baseline: 2.6630x; 1.8971x over previous
#include <cuda_runtime.h>

#define NN   4096
#define FEAT 1024
#define GC   10
#define HD   5

// Scratch (no allocations allowed)
__device__ float g_s[NN];           // D^{-1/2} diagonal
__device__ float g_M[NN * GC];      // projected features (input to Ahat@)
__device__ float g_H[NN * GC];      // selu(Ahat@M) output
__device__ float g_Hp[NN * 12];     // padded copy of g_H (stride 12) for k_lstm

__device__ __forceinline__ float tanha(float x) {
    float y;
    asm("tanh.approx.f32 %0, %1;" : "=f"(y) : "f"(x));
    return y;
}
__device__ __forceinline__ float siga(float x) {
    return fmaf(0.5f, tanha(0.5f * x), 0.5f);
}
__device__ __forceinline__ float sig_exact(float v) {
    return 1.0f / (1.0f + __expf(-v));
}
__device__ __forceinline__ float seluf(float v) {
    return v > 0.0f ? 1.0507009873554805f * v
                    : 1.7580993408473766f * (__expf(v) - 1.0f);
}

// ---------------------------------------------------------------------------
// K1: row sums of A -> s_i
// ---------------------------------------------------------------------------
__global__ void k_rowsum(const float* __restrict__ A) {
    int row = blockIdx.x;
    const float4* a4 = (const float4*)(A + (size_t)row * NN);
    float s = 0.0f;
    for (int i = threadIdx.x; i < NN / 4; i += blockDim.x) {
        float4 v = a4[i];
        s += (v.x + v.y) + (v.z + v.w);
    }
    __shared__ float red[8];
    #pragma unroll
    for (int o = 16; o; o >>= 1) s += __shfl_xor_sync(0xffffffffu, s, o);
    if ((threadIdx.x & 31) == 0) red[threadIdx.x >> 5] = s;
    __syncthreads();
    if (threadIdx.x < 32) {
        float v = (threadIdx.x < (blockDim.x >> 5)) ? red[threadIdx.x] : 0.0f;
        #pragma unroll
        for (int o = 4; o; o >>= 1) v += __shfl_xor_sync(0xffffffffu, v, o);
        if (threadIdx.x == 0) g_s[row] = v > 0.0f ? rsqrtf(v) : 0.0f;
    }
}

// ---------------------------------------------------------------------------
// K2: g_M = X @ W0^T
// ---------------------------------------------------------------------------
__global__ void k_xw(const float* __restrict__ X, const float* __restrict__ W0) {
    int row  = blockIdx.x * blockDim.y + threadIdx.y;
    int lane = threadIdx.x;
    const float* xr = X + (size_t)row * FEAT;
    float acc[GC];
    #pragma unroll
    for (int k = 0; k < GC; k++) acc[k] = 0.0f;
    for (int m = 0; m < FEAT / 32; m++) {
        int j = m * 32 + lane;
        float xv = xr[j];
        #pragma unroll
        for (int k = 0; k < GC; k++) acc[k] += xv * W0[k * FEAT + j];
    }
    #pragma unroll
    for (int k = 0; k < GC; k++) {
        #pragma unroll
        for (int o = 16; o; o >>= 1)
            acc[k] += __shfl_xor_sync(0xffffffffu, acc[k], o);
    }
    if (lane == 0) {
        #pragma unroll
        for (int k = 0; k < GC; k++) g_M[row * GC + k] = acc[k];
    }
}

// ---------------------------------------------------------------------------
// K3: g_H = selu( Ahat @ g_M );  also writes padded copy g_Hp
// ---------------------------------------------------------------------------
#define RPB 16
#define JC  1024
__global__ void k_spmm(const float* __restrict__ A) {
    __shared__ __align__(16) float Zs[JC * 12];
    int rowbase = blockIdx.x * RPB;
    int sub = threadIdx.x & 15;
    int r   = threadIdx.x >> 4;
    int row = rowbase + r;
    float acc[GC];
    #pragma unroll
    for (int k = 0; k < GC; k++) acc[k] = 0.0f;

    for (int jb = 0; jb < NN; jb += JC) {
        __syncthreads();
        for (int t = threadIdx.x; t < JC; t += blockDim.x) {
            int j = jb + t;
            float sj = g_s[j];
            #pragma unroll
            for (int k = 0; k < GC; k++) Zs[t * 12 + k] = sj * g_M[j * GC + k];
        }
        __syncthreads();
        const float* ar = A + (size_t)row * NN + jb;
        for (int m = 0; m < JC / 16; m++) {
            int jj = sub + m * 16;
            float a = ar[jj];
            float4 z0 = *(const float4*)&Zs[jj * 12];
            float4 z1 = *(const float4*)&Zs[jj * 12 + 4];
            float2 z2 = *(const float2*)&Zs[jj * 12 + 8];
            acc[0] += a * z0.x; acc[1] += a * z0.y;
            acc[2] += a * z0.z; acc[3] += a * z0.w;
            acc[4] += a * z1.x; acc[5] += a * z1.y;
            acc[6] += a * z1.z; acc[7] += a * z1.w;
            acc[8] += a * z2.x; acc[9] += a * z2.y;
        }
    }
    #pragma unroll
    for (int k = 0; k < GC; k++) {
        #pragma unroll
        for (int o = 8; o; o >>= 1)
            acc[k] += __shfl_xor_sync(0xffffffffu, acc[k], o);
    }
    if (sub == 0) {
        float si = g_s[row];
        #pragma unroll
        for (int k = 0; k < GC; k++) {
            float v = si * acc[k] + si * si * g_M[row * GC + k];
            float sv = seluf(v);
            g_H[row * GC + k]  = sv;
            g_Hp[row * 12 + k] = sv;
        }
    }
}

// ---------------------------------------------------------------------------
// K4: g_M = g_H @ W^T
// ---------------------------------------------------------------------------
__global__ void k_hw(const float* __restrict__ W) {
    int i = blockIdx.x * blockDim.x + threadIdx.x;
    if (i >= NN) return;
    float h[GC];
    #pragma unroll
    for (int k = 0; k < GC; k++) h[k] = g_H[i * GC + k];
    #pragma unroll
    for (int ko = 0; ko < GC; ko++) {
        float s = 0.0f;
        #pragma unroll
        for (int k = 0; k < GC; k++) s += h[k] * W[ko * GC + k];
        g_M[i * GC + ko] = s;
    }
}

// ---------------------------------------------------------------------------
// K5: LSTM. Encoder = wavefront-pipelined across layers (layer l processes
// token w-l at wavefront w; all 3 layer lane-groups compute concurrently,
// one cell's worth of math per lane-group per wavefront). Inputs prefetched
// from L2 (g_Hp, padded stride 12) with distance-2 register double buffer.
// Decoder = serial 3-stage, 20-lane layout (2 gates/lane), weights for all
// layers resident per lane.
// ---------------------------------------------------------------------------
__global__ void __launch_bounds__(32, 1) k_lstm(
    const float* __restrict__ Wih_g, const float* __restrict__ Whh_g,
    const float* __restrict__ bih_g, const float* __restrict__ bhh_g,
    const float* __restrict__ h0_g,  const float* __restrict__ c0_g,
    const float* __restrict__ tok_g, const float* __restrict__ Wo_g,
    const float* __restrict__ bo_g,  float* __restrict__ out)
{
    const int lane = threadIdx.x;
    const unsigned FM = 0xffffffffu;

    // =====================  ENCODER (wavefront pipeline)  ====================
    const int li   = (lane < 30) ? lane : 29;
    const int myl  = li / 10;
    const int rr   = li % 10;
    const int dsel = rr / 5;
    const int j    = rr % 5;
    const int kc   = 2 * myl + dsel;

    float wih[4][GC], whh[4][HD], bias[4];
    #pragma unroll
    for (int q = 0; q < 4; q++) {
        int row = kc * 20 + q * 5 + j;
        #pragma unroll
        for (int i = 0; i < GC; i++) wih[q][i] = Wih_g[row * GC + i];
        #pragma unroll
        for (int i = 0; i < HD; i++) whh[q][i] = Whh_g[row * HD + i];
        bias[q] = bih_g[row] + bhh_g[row];
    }
    float h = h0_g[kc * HD + j];
    float c = c0_g[kc * HD + j];
    float hp[HD];
    #pragma unroll
    for (int i = 0; i < HD; i++) hp[i] = h0_g[kc * HD + i];

    // distance-2 prefetch pipeline: xin = row w, buf = row w+1, nxt = row w+2
    float xin[GC], buf[GC];
    #pragma unroll
    for (int i = 0; i < GC; i++) xin[i] = g_Hp[i];           // row 0
    #pragma unroll
    for (int i = 0; i < GC; i++) buf[i] = g_Hp[12 + i];      // row 1

    const int pullbase = (myl == 0) ? 0 : (myl - 1) * 10;
    const int hpbase   = myl * 10 + dsel * 5;

    for (int w = 0; w < NN + 2; w++) {
        // issue load of row w+2 now; consumed ~2 wavefronts (~350 cyc) later
        int nrow = (w + 2 < NN) ? (w + 2) : (NN - 1);
        float4 ra = *(const float4*)&g_Hp[nrow * 12];
        float4 rb = *(const float4*)&g_Hp[nrow * 12 + 4];
        float2 rc = *(const float2*)&g_Hp[nrow * 12 + 8];

        bool valid = (w >= myl) && (w - myl < NN);

        float a0[4], a1[4], a2[4];
        #pragma unroll
        for (int q = 0; q < 4; q++) { a0[q] = bias[q]; a1[q] = 0.0f; a2[q] = 0.0f; }
        #pragma unroll
        for (int i = 0; i < 5; i++) {
            #pragma unroll
            for (int q = 0; q < 4; q++) a0[q] = fmaf(wih[q][i], xin[i], a0[q]);
        }
        #pragma unroll
        for (int i = 5; i < 10; i++) {
            #pragma unroll
            for (int q = 0; q < 4; q++) a1[q] = fmaf(wih[q][i], xin[i], a1[q]);
        }
        #pragma unroll
        for (int i = 0; i < 5; i++) {
            #pragma unroll
            for (int q = 0; q < 4; q++) a2[q] = fmaf(whh[q][i], hp[i], a2[q]);
        }
        float gi = (a0[0] + a1[0]) + a2[0];
        float gf = (a0[1] + a1[1]) + a2[1];
        float gg = (a0[2] + a1[2]) + a2[2];
        float go = (a0[3] + a1[3]) + a2[3];
        float ai = siga(gi), af = siga(gf), ag = tanha(gg), ao = siga(go);
        float cn = fmaf(af, c, ai * ag);
        float hn = ao * tanha(cn);
        c = valid ? cn : c;
        h = valid ? hn : h;

        // pulls: input for my layer comes from layer myl-1's broadcast
        float pull[GC];
        #pragma unroll
        for (int m = 0; m < GC; m++)
            pull[m] = __shfl_sync(FM, h, pullbase + m);
        // refresh my recurrent h_prev from my own layer's broadcast
        #pragma unroll
        for (int i = 0; i < HD; i++)
            hp[i] = __shfl_sync(FM, h, hpbase + i);

        #pragma unroll
        for (int m = 0; m < GC; m++)
            xin[m] = (myl == 0) ? buf[m] : pull[m];
        buf[0] = ra.x; buf[1] = ra.y; buf[2] = ra.z; buf[3] = ra.w;
        buf[4] = rb.x; buf[5] = rb.y; buf[6] = rb.z; buf[7] = rb.w;
        buf[8] = rc.x; buf[9] = rc.y;
    }

    // =====================  DECODER (serial, 20-lane)  =======================
    // lane = gh*10 + pp ; pp = cell (d = pp/5, j = pp%5); gh=0 -> gates (i,f),
    // gh=1 -> gates (g,o). Weights for all 3 layers resident per lane.
    const int dl  = (lane < 20) ? lane : 19;
    const int pp  = dl % 10;
    const int gh  = dl / 10;
    const int dd  = pp / 5;
    const int jd  = pp % 5;

    float wA[3][GC], vA[3][HD], bA[3];
    float wB[3][GC], vB[3][HD], bB[3];
    #pragma unroll
    for (int l = 0; l < 3; l++) {
        int kc2  = 2 * l + dd;
        int rowA = kc2 * 20 + gh * 10 + jd;
        int rowB = rowA + 5;
        #pragma unroll
        for (int i = 0; i < GC; i++) { wA[l][i] = Wih_g[rowA * GC + i];
                                       wB[l][i] = Wih_g[rowB * GC + i]; }
        #pragma unroll
        for (int i = 0; i < HD; i++) { vA[l][i] = Whh_g[rowA * HD + i];
                                       vB[l][i] = Whh_g[rowB * HD + i]; }
        bA[l] = bih_g[rowA] + bhh_g[rowA];
        bB[l] = bih_g[rowB] + bhh_g[rowB];
    }
    // initial decoder state from encoder-final state (encoder lane layout)
    float cD[3], hpD[3][HD];
    #pragma unroll
    for (int l = 0; l < 3; l++) {
        cD[l] = __shfl_sync(FM, c, l * 10 + pp);
        #pragma unroll
        for (int i = 0; i < HD; i++)
            hpD[l][i] = __shfl_sync(FM, h, l * 10 + dd * 5 + i);
    }
    float wov[GC];
    #pragma unroll
    for (int i = 0; i < GC; i++) wov[i] = Wo_g[i];
    const float bo0 = bo_g[0];

    float x[GC];
    #pragma unroll
    for (int i = 0; i < GC; i++) x[i] = tok_g[i];

    for (int t = 0; t < NN; t++) {
        #pragma unroll
        for (int l = 0; l < 3; l++) {
            float pA0 = bA[l], pA1 = 0.0f, pA2 = 0.0f;
            float pB0 = bB[l], pB1 = 0.0f, pB2 = 0.0f;
            #pragma unroll
            for (int i = 0; i < 5; i++) {
                pA0 = fmaf(wA[l][i], x[i], pA0);
                pB0 = fmaf(wB[l][i], x[i], pB0);
            }
            #pragma unroll
            for (int i = 5; i < 10; i++) {
                pA1 = fmaf(wA[l][i], x[i], pA1);
                pB1 = fmaf(wB[l][i], x[i], pB1);
            }
            #pragma unroll
            for (int i = 0; i < 5; i++) {
                pA2 = fmaf(vA[l][i], hpD[l][i], pA2);
                pB2 = fmaf(vB[l][i], hpD[l][i], pB2);
            }
            float gA = (pA0 + pA1) + pA2;
            float gB = (pB0 + pB1) + pB2;
            // gh=0: A=i (sig), B=f (sig); gh=1: A=g (tanh), B=o (sig)
            float uA = gh ? gA : 0.5f * gA;
            float tA = tanha(uA);
            float aA = gh ? tA : fmaf(0.5f, tA, 0.5f);
            float aB = siga(gB);
            float ag = __shfl_sync(FM, aA, 10 + pp);
            float ao = __shfl_sync(FM, aB, 10 + pp);
            float cn = fmaf(aB, cD[l], aA * ag);   // af=aB, ai=aA on lanes<10
            float hn = ao * tanha(cn);
            cD[l] = cn;
            #pragma unroll
            for (int m = 0; m < GC; m++)
                x[m] = __shfl_sync(FM, hn, m);
            #pragma unroll
            for (int i = 0; i < HD; i++)
                hpD[l][i] = dd ? x[5 + i] : x[i];
        }
        float z = bo0;
        #pragma unroll
        for (int i = 0; i < GC; i++) z = fmaf(x[i], wov[i], z);
        if (lane == 0) out[t] = sig_exact(z);
    }
}

// ---------------------------------------------------------------------------
extern "C" void kernel_launch(void* const* d_in, const int* in_sizes, int n_in,
                              void* d_out, int out_size)
{
    const float* A   = (const float*)d_in[0];
    const float* X   = (const float*)d_in[1];
    const float* W0  = (const float*)d_in[2];
    const float* W1  = (const float*)d_in[3];
    const float* W2  = (const float*)d_in[4];
    const float* Wih = (const float*)d_in[5];
    const float* Whh = (const float*)d_in[6];
    const float* bih = (const float*)d_in[7];
    const float* bhh = (const float*)d_in[8];
    const float* h0  = (const float*)d_in[9];
    const float* c0  = (const float*)d_in[10];
    const float* tok = (const float*)d_in[11];
    const float* Wo  = (const float*)d_in[12];
    const float* bo  = (const float*)d_in[13];
    float* out = (float*)d_out;
    (void)in_sizes; (void)n_in; (void)out_size;

    k_rowsum<<<NN, 256>>>(A);
    k_xw<<<NN / 8, dim3(32, 8)>>>(X, W0);        // g_M = X @ W0^T
    k_spmm<<<NN / RPB, 256>>>(A);                // g_H = selu(Ahat @ g_M)
    k_hw<<<(NN + 255) / 256, 256>>>(W1);         // g_M = g_H @ W1^T
    k_spmm<<<NN / RPB, 256>>>(A);
    k_hw<<<(NN + 255) / 256, 256>>>(W2);         // g_M = g_H @ W2^T
    k_spmm<<<NN / RPB, 256>>>(A);                // g_H/g_Hp = H3
    k_lstm<<<1, 32>>>(Wih, Whh, bih, bhh, h0, c0, tok, Wo, bo, out);
}

// round 5
// speedup vs baseline: 2.8650x; 1.0758x over previous
#include <cuda_runtime.h>

#define NN   4096
#define FEAT 1024
#define GC   10
#define HD   5

// Scratch (no allocations allowed)
__device__ float g_s[NN];           // D^{-1/2} diagonal
__device__ float g_Ma[NN * GC];     // ping buffer
__device__ float g_Mb[NN * GC];     // pong buffer
__device__ float g_Hp[NN * 12];     // padded H3 (stride 12) for encoder
__device__ float g_hfin[32];        // encoder-final h (encoder lane layout)
__device__ float g_cfin[32];        // encoder-final c

__device__ __forceinline__ float tanha(float x) {
    float y;
    asm("tanh.approx.f32 %0, %1;" : "=f"(y) : "f"(x));
    return y;
}
__device__ __forceinline__ float siga(float x) {
    return fmaf(0.5f, tanha(0.5f * x), 0.5f);
}
__device__ __forceinline__ float sig_exact(float v) {
    return 1.0f / (1.0f + __expf(-v));
}
__device__ __forceinline__ float seluf(float v) {
    return v > 0.0f ? 1.0507009873554805f * v
                    : 1.7580993408473766f * (__expf(v) - 1.0f);
}

// ---------------------------------------------------------------------------
// K1: fused rowsum (blocks 0..NN-1) + X@W0^T (blocks NN..NN+511)
// ---------------------------------------------------------------------------
__global__ void k_pre(const float* __restrict__ A, const float* __restrict__ X,
                      const float* __restrict__ W0) {
    if (blockIdx.x < NN) {
        int row = blockIdx.x;
        const float4* a4 = (const float4*)(A + (size_t)row * NN);
        float s = 0.0f;
        for (int i = threadIdx.x; i < NN / 4; i += blockDim.x) {
            float4 v = a4[i];
            s += (v.x + v.y) + (v.z + v.w);
        }
        __shared__ float red[8];
        #pragma unroll
        for (int o = 16; o; o >>= 1) s += __shfl_xor_sync(0xffffffffu, s, o);
        if ((threadIdx.x & 31) == 0) red[threadIdx.x >> 5] = s;
        __syncthreads();
        if (threadIdx.x < 32) {
            float v = (threadIdx.x < (blockDim.x >> 5)) ? red[threadIdx.x] : 0.0f;
            #pragma unroll
            for (int o = 4; o; o >>= 1) v += __shfl_xor_sync(0xffffffffu, v, o);
            if (threadIdx.x == 0) g_s[row] = v > 0.0f ? rsqrtf(v) : 0.0f;
        }
    } else {
        int row  = (blockIdx.x - NN) * 8 + (threadIdx.x >> 5);
        int lane = threadIdx.x & 31;
        const float* xr = X + (size_t)row * FEAT;
        float acc[GC];
        #pragma unroll
        for (int k = 0; k < GC; k++) acc[k] = 0.0f;
        for (int m = 0; m < FEAT / 32; m++) {
            int j = m * 32 + lane;
            float xv = xr[j];
            #pragma unroll
            for (int k = 0; k < GC; k++) acc[k] += xv * W0[k * FEAT + j];
        }
        #pragma unroll
        for (int k = 0; k < GC; k++) {
            #pragma unroll
            for (int o = 16; o; o >>= 1)
                acc[k] += __shfl_xor_sync(0xffffffffu, acc[k], o);
        }
        if (lane == 0) {
            #pragma unroll
            for (int k = 0; k < GC; k++) g_Ma[row * GC + k] = acc[k];
        }
    }
}

// ---------------------------------------------------------------------------
// K2: out = selu(Ahat @ in) [@ W^T if W, else padded stride-12 write]
// ---------------------------------------------------------------------------
#define RPB 16
#define JC  1024
__global__ void k_spmm(const float* __restrict__ A, const float* __restrict__ in,
                       float* __restrict__ out, const float* __restrict__ W) {
    __shared__ __align__(16) float Zs[JC * 12];
    int rowbase = blockIdx.x * RPB;
    int sub = threadIdx.x & 15;
    int r   = threadIdx.x >> 4;
    int row = rowbase + r;
    float acc[GC];
    #pragma unroll
    for (int k = 0; k < GC; k++) acc[k] = 0.0f;

    for (int jb = 0; jb < NN; jb += JC) {
        __syncthreads();
        for (int t = threadIdx.x; t < JC; t += blockDim.x) {
            int j = jb + t;
            float sj = g_s[j];
            #pragma unroll
            for (int k = 0; k < GC; k++) Zs[t * 12 + k] = sj * in[j * GC + k];
        }
        __syncthreads();
        const float* ar = A + (size_t)row * NN + jb;
        for (int m = 0; m < JC / 16; m++) {
            int jj = sub + m * 16;
            float a = ar[jj];
            float4 z0 = *(const float4*)&Zs[jj * 12];
            float4 z1 = *(const float4*)&Zs[jj * 12 + 4];
            float2 z2 = *(const float2*)&Zs[jj * 12 + 8];
            acc[0] += a * z0.x; acc[1] += a * z0.y;
            acc[2] += a * z0.z; acc[3] += a * z0.w;
            acc[4] += a * z1.x; acc[5] += a * z1.y;
            acc[6] += a * z1.z; acc[7] += a * z1.w;
            acc[8] += a * z2.x; acc[9] += a * z2.y;
        }
    }
    #pragma unroll
    for (int k = 0; k < GC; k++) {
        #pragma unroll
        for (int o = 8; o; o >>= 1)
            acc[k] += __shfl_xor_sync(0xffffffffu, acc[k], o);
    }
    if (sub == 0) {
        float si = g_s[row];
        float sv[GC];
        #pragma unroll
        for (int k = 0; k < GC; k++) {
            float v = si * acc[k] + si * si * in[row * GC + k];
            sv[k] = seluf(v);
        }
        if (W) {
            #pragma unroll
            for (int ko = 0; ko < GC; ko++) {
                float s = 0.0f;
                #pragma unroll
                for (int k = 0; k < GC; k++) s = fmaf(sv[k], W[ko * GC + k], s);
                out[row * GC + ko] = s;
            }
        } else {
            #pragma unroll
            for (int k = 0; k < GC; k++) out[row * 12 + k] = sv[k];
        }
    }
}

// ---------------------------------------------------------------------------
// K3: encoder — wavefront pipeline across layers, single warp.
// ---------------------------------------------------------------------------
__global__ void __launch_bounds__(32, 1) k_enc(
    const float* __restrict__ Wih_g, const float* __restrict__ Whh_g,
    const float* __restrict__ bih_g, const float* __restrict__ bhh_g,
    const float* __restrict__ h0_g,  const float* __restrict__ c0_g)
{
    const int lane = threadIdx.x;
    const unsigned FM = 0xffffffffu;
    const int li   = (lane < 30) ? lane : 29;
    const int myl  = li / 10;
    const int rr   = li % 10;
    const int dsel = rr / 5;
    const int j    = rr % 5;
    const int kc   = 2 * myl + dsel;

    float wih[4][GC], whh[4][HD], bias[4];
    #pragma unroll
    for (int q = 0; q < 4; q++) {
        int row = kc * 20 + q * 5 + j;
        #pragma unroll
        for (int i = 0; i < GC; i++) wih[q][i] = Wih_g[row * GC + i];
        #pragma unroll
        for (int i = 0; i < HD; i++) whh[q][i] = Whh_g[row * HD + i];
        bias[q] = bih_g[row] + bhh_g[row];
    }
    float h = h0_g[kc * HD + j];
    float c = c0_g[kc * HD + j];
    float hp[HD];
    #pragma unroll
    for (int i = 0; i < HD; i++) hp[i] = h0_g[kc * HD + i];

    float xin[GC], buf[GC];
    #pragma unroll
    for (int i = 0; i < GC; i++) xin[i] = g_Hp[i];
    #pragma unroll
    for (int i = 0; i < GC; i++) buf[i] = g_Hp[12 + i];

    const int pullbase = (myl == 0) ? 0 : (myl - 1) * 10;
    const int hpbase   = myl * 10 + dsel * 5;

    for (int w = 0; w < NN + 2; w++) {
        int nrow = (w + 2 < NN) ? (w + 2) : (NN - 1);
        float4 ra = *(const float4*)&g_Hp[nrow * 12];
        float4 rb = *(const float4*)&g_Hp[nrow * 12 + 4];
        float2 rc = *(const float2*)&g_Hp[nrow * 12 + 8];

        bool valid = (w >= myl) && (w - myl < NN);

        float a0[4], a1[4], a2[4];
        #pragma unroll
        for (int q = 0; q < 4; q++) { a0[q] = bias[q]; a1[q] = 0.0f; a2[q] = 0.0f; }
        #pragma unroll
        for (int i = 0; i < 5; i++) {
            #pragma unroll
            for (int q = 0; q < 4; q++) a0[q] = fmaf(wih[q][i], xin[i], a0[q]);
        }
        #pragma unroll
        for (int i = 5; i < 10; i++) {
            #pragma unroll
            for (int q = 0; q < 4; q++) a1[q] = fmaf(wih[q][i], xin[i], a1[q]);
        }
        #pragma unroll
        for (int i = 0; i < 5; i++) {
            #pragma unroll
            for (int q = 0; q < 4; q++) a2[q] = fmaf(whh[q][i], hp[i], a2[q]);
        }
        float gi = (a0[0] + a1[0]) + a2[0];
        float gf = (a0[1] + a1[1]) + a2[1];
        float gg = (a0[2] + a1[2]) + a2[2];
        float go = (a0[3] + a1[3]) + a2[3];
        float ai = siga(gi), af = siga(gf), ag = tanha(gg), ao = siga(go);
        float cn = fmaf(af, c, ai * ag);
        float hn = ao * tanha(cn);
        c = valid ? cn : c;
        h = valid ? hn : h;

        float pull[GC];
        #pragma unroll
        for (int m = 0; m < GC; m++)
            pull[m] = __shfl_sync(FM, h, pullbase + m);
        #pragma unroll
        for (int i = 0; i < HD; i++)
            hp[i] = __shfl_sync(FM, h, hpbase + i);

        #pragma unroll
        for (int m = 0; m < GC; m++)
            xin[m] = (myl == 0) ? buf[m] : pull[m];
        buf[0] = ra.x; buf[1] = ra.y; buf[2] = ra.z; buf[3] = ra.w;
        buf[4] = rb.x; buf[5] = rb.y; buf[6] = rb.z; buf[7] = rb.w;
        buf[8] = rc.x; buf[9] = rc.y;
    }

    if (lane < 30) {
        g_hfin[lane] = h;
        g_cfin[lane] = c;
    }
}

// ---------------------------------------------------------------------------
// K4: decoder — serial autoregressive, 20-lane layout (2 gates/lane).
// ---------------------------------------------------------------------------
__global__ void __launch_bounds__(32, 1) k_dec(
    const float* __restrict__ Wih_g, const float* __restrict__ Whh_g,
    const float* __restrict__ bih_g, const float* __restrict__ bhh_g,
    const float* __restrict__ tok_g, const float* __restrict__ Wo_g,
    const float* __restrict__ bo_g,  float* __restrict__ out)
{
    const int lane = threadIdx.x;
    const unsigned FM = 0xffffffffu;
    const int dl  = (lane < 20) ? lane : 19;
    const int pp  = dl % 10;
    const int gh  = dl / 10;
    const int dd  = pp / 5;
    const int jd  = pp % 5;

    float wA[3][GC], vA[3][HD], bA[3];
    float wB[3][GC], vB[3][HD], bB[3];
    #pragma unroll
    for (int l = 0; l < 3; l++) {
        int kc2  = 2 * l + dd;
        int rowA = kc2 * 20 + gh * 10 + jd;
        int rowB = rowA + 5;
        #pragma unroll
        for (int i = 0; i < GC; i++) { wA[l][i] = Wih_g[rowA * GC + i];
                                       wB[l][i] = Wih_g[rowB * GC + i]; }
        #pragma unroll
        for (int i = 0; i < HD; i++) { vA[l][i] = Whh_g[rowA * HD + i];
                                       vB[l][i] = Whh_g[rowB * HD + i]; }
        bA[l] = bih_g[rowA] + bhh_g[rowA];
        bB[l] = bih_g[rowB] + bhh_g[rowB];
    }
    float cD[3], hpD[3][HD];
    #pragma unroll
    for (int l = 0; l < 3; l++) {
        cD[l] = g_cfin[l * 10 + pp];
        #pragma unroll
        for (int i = 0; i < HD; i++)
            hpD[l][i] = g_hfin[l * 10 + dd * 5 + i];
    }
    float wov[GC];
    #pragma unroll
    for (int i = 0; i < GC; i++) wov[i] = Wo_g[i];
    const float bo0 = bo_g[0];

    float x[GC];
    #pragma unroll
    for (int i = 0; i < GC; i++) x[i] = tok_g[i];

    for (int t = 0; t < NN; t++) {
        #pragma unroll
        for (int l = 0; l < 3; l++) {
            float pA0 = bA[l], pA1 = 0.0f, pA2 = 0.0f;
            float pB0 = bB[l], pB1 = 0.0f, pB2 = 0.0f;
            #pragma unroll
            for (int i = 0; i < 5; i++) {
                pA0 = fmaf(wA[l][i], x[i], pA0);
                pB0 = fmaf(wB[l][i], x[i], pB0);
            }
            #pragma unroll
            for (int i = 5; i < 10; i++) {
                pA1 = fmaf(wA[l][i], x[i], pA1);
                pB1 = fmaf(wB[l][i], x[i], pB1);
            }
            #pragma unroll
            for (int i = 0; i < 5; i++) {
                pA2 = fmaf(vA[l][i], hpD[l][i], pA2);
                pB2 = fmaf(vB[l][i], hpD[l][i], pB2);
            }
            float gA = (pA0 + pA1) + pA2;
            float gB = (pB0 + pB1) + pB2;
            float uA = gh ? gA : 0.5f * gA;
            float tA = tanha(uA);
            float aA = gh ? tA : fmaf(0.5f, tA, 0.5f);
            float aB = siga(gB);
            float ag = __shfl_sync(FM, aA, 10 + pp);
            float ao = __shfl_sync(FM, aB, 10 + pp);
            float cn = fmaf(aB, cD[l], aA * ag);
            float hn = ao * tanha(cn);
            cD[l] = cn;
            #pragma unroll
            for (int m = 0; m < GC; m++)
                x[m] = __shfl_sync(FM, hn, m);
            #pragma unroll
            for (int i = 0; i < HD; i++)
                hpD[l][i] = dd ? x[5 + i] : x[i];
        }
        float z = bo0;
        #pragma unroll
        for (int i = 0; i < GC; i++) z = fmaf(x[i], wov[i], z);
        if (lane == 0) out[t] = sig_exact(z);
    }
}

// ---------------------------------------------------------------------------
extern "C" void kernel_launch(void* const* d_in, const int* in_sizes, int n_in,
                              void* d_out, int out_size)
{
    const float* A   = (const float*)d_in[0];
    const float* X   = (const float*)d_in[1];
    const float* W0  = (const float*)d_in[2];
    const float* W1  = (const float*)d_in[3];
    const float* W2  = (const float*)d_in[4];
    const float* Wih = (const float*)d_in[5];
    const float* Whh = (const float*)d_in[6];
    const float* bih = (const float*)d_in[7];
    const float* bhh = (const float*)d_in[8];
    const float* h0  = (const float*)d_in[9];
    const float* c0  = (const float*)d_in[10];
    const float* tok = (const float*)d_in[11];
    const float* Wo  = (const float*)d_in[12];
    const float* bo  = (const float*)d_in[13];
    float* out = (float*)d_out;
    (void)in_sizes; (void)n_in; (void)out_size;

    float *gMa, *gMb, *gHp;
    cudaGetSymbolAddress((void**)&gMa, g_Ma);
    cudaGetSymbolAddress((void**)&gMb, g_Mb);
    cudaGetSymbolAddress((void**)&gHp, g_Hp);

    k_pre<<<NN + 512, 256>>>(A, X, W0);              // g_s + g_Ma = X@W0^T
    k_spmm<<<NN / RPB, 256>>>(A, gMa, gMb, W1);      // g_Mb = selu(Ahat@g_Ma)@W1^T
    k_spmm<<<NN / RPB, 256>>>(A, gMb, gMa, W2);      // g_Ma = selu(Ahat@g_Mb)@W2^T
    k_spmm<<<NN / RPB, 256>>>(A, gMa, gHp, nullptr); // g_Hp = H3 (padded)
    k_enc<<<1, 32>>>(Wih, Whh, bih, bhh, h0, c0);
    k_dec<<<1, 32>>>(Wih, Whh, bih, bhh, tok, Wo, bo, out);
}